// round 7
// baseline (speedup 1.0000x reference)
#include <cuda_runtime.h>
#include <math.h>

#define DIM 16777216
#define NVEC (DIM / 4)          // 4,194,304 float4 elements
#define THREADS 256
#define BLOCKS (NVEC / THREADS) // 16384

// Zero-initialized at module load; the last finishing block resets them at the
// end of every launch, so each launch sees zeros (graph-replay deterministic).
__device__ float        g_sum_dev2;
__device__ float        g_sum_css2;
__device__ unsigned int g_ticket;

__global__ void __launch_bounds__(THREADS) ni_fused_kernel(
    const float* __restrict__ css_in,   // (4, DIM)
    const float* __restrict__ narr,     // (DIM,)
    const float* __restrict__ tonic,    // (DIM,)
    const float* __restrict__ fast_p,   // scalar
    const float* __restrict__ slow_p,   // scalar
    float* __restrict__ out)            // [0:DIM)=new_narrative, [DIM:2DIM)=velocity, [2DIM:2DIM+3)=scalars
{
    const int i = blockIdx.x * blockDim.x + threadIdx.x;  // float4 index

    const float4* a0 = reinterpret_cast<const float4*>(css_in);
    const float4* a1 = a0 + NVEC;
    const float4* a2 = a1 + NVEC;
    const float4* a3 = a2 + NVEC;
    const float4* n4 = reinterpret_cast<const float4*>(narr);
    const float4* t4 = reinterpret_cast<const float4*>(tonic);
    float4* out_nn  = reinterpret_cast<float4*>(out);
    float4* out_vel = out_nn + NVEC;

    float4 v0 = a0[i];
    float4 v1 = a1[i];
    float4 v2 = a2[i];
    float4 v3 = a3[i];
    float4 n  = n4[i];
    float4 t  = t4[i];

    float dev2 = 0.0f;
    float c2   = 0.0f;
    float4 nn, vel;

    {
        float css = (v0.x + v1.x + v2.x + v3.x) * 0.25f;
        float d   = css - n.x;
        dev2 = fmaf(d, d, dev2);  c2 = fmaf(css, css, c2);
        nn.x  = fmaf(n.x, 0.99f, fmaf(css, 0.01f, t.x));
        vel.x = nn.x - n.x;
    }
    {
        float css = (v0.y + v1.y + v2.y + v3.y) * 0.25f;
        float d   = css - n.y;
        dev2 = fmaf(d, d, dev2);  c2 = fmaf(css, css, c2);
        nn.y  = fmaf(n.y, 0.99f, fmaf(css, 0.01f, t.y));
        vel.y = nn.y - n.y;
    }
    {
        float css = (v0.z + v1.z + v2.z + v3.z) * 0.25f;
        float d   = css - n.z;
        dev2 = fmaf(d, d, dev2);  c2 = fmaf(css, css, c2);
        nn.z  = fmaf(n.z, 0.99f, fmaf(css, 0.01f, t.z));
        vel.z = nn.z - n.z;
    }
    {
        float css = (v0.w + v1.w + v2.w + v3.w) * 0.25f;
        float d   = css - n.w;
        dev2 = fmaf(d, d, dev2);  c2 = fmaf(css, css, c2);
        nn.w  = fmaf(n.w, 0.99f, fmaf(css, 0.01f, t.w));
        vel.w = nn.w - n.w;
    }

    out_nn[i]  = nn;
    out_vel[i] = vel;

    // Warp-level reduce both sums
    #pragma unroll
    for (int off = 16; off > 0; off >>= 1) {
        dev2 += __shfl_down_sync(0xFFFFFFFFu, dev2, off);
        c2   += __shfl_down_sync(0xFFFFFFFFu, c2,   off);
    }

    __shared__ float s_dev[THREADS / 32];
    __shared__ float s_css[THREADS / 32];
    const int lane = threadIdx.x & 31;
    const int wid  = threadIdx.x >> 5;
    if (lane == 0) { s_dev[wid] = dev2; s_css[wid] = c2; }
    __syncthreads();

    if (wid == 0) {
        dev2 = (lane < THREADS / 32) ? s_dev[lane] : 0.0f;
        c2   = (lane < THREADS / 32) ? s_css[lane] : 0.0f;
        #pragma unroll
        for (int off = 4; off > 0; off >>= 1) {
            dev2 += __shfl_down_sync(0xFFFFFFFFu, dev2, off);
            c2   += __shfl_down_sync(0xFFFFFFFFu, c2,   off);
        }
        if (lane == 0) {
            atomicAdd(&g_sum_dev2, dev2);
            atomicAdd(&g_sum_css2, c2);
            __threadfence();  // make sums visible before ticket increment
            unsigned int tk = atomicAdd(&g_ticket, 1u);
            if (tk == (unsigned int)(BLOCKS - 1)) {
                // Last block: compute scalar epilogue, then reset state.
                const float sum_dev2 = atomicAdd(&g_sum_dev2, 0.0f);
                const float sum_css2 = atomicAdd(&g_sum_css2, 0.0f);
                const float dev_norm = sqrtf(sum_dev2);
                const float css_norm = sqrtf(sum_css2);
                const float fast = fast_p[0];
                const float slow = slow_p[0];

                const float consistency_loss = 0.1f * dev_norm;

                const float input_gate = fminf(1.0f, css_norm);
                const float delta_fast = 0.01f / (1.0f + fast * 5.0f) * input_gate;
                const float fast_new   = fminf(fast * 0.9995f + delta_fast, 0.7f);

                const float schema_fit  = fminf(fmaxf(1.0f - dev_norm, 0.0f), 1.0f);
                const float schema_mult = 1.0f + 15.0f * schema_fit * schema_fit;
                const float delta_slow  = 0.001f / (1.0f + slow * 5.0f) * schema_mult;
                const float slow_new    = fminf(slow + delta_slow, 1.0f);

                const float identity_strength = fminf(fast_new + slow_new, 1.0f);

                out[2 * DIM + 0] = consistency_loss;
                out[2 * DIM + 1] = identity_strength;
                out[2 * DIM + 2] = dev_norm;

                // Reset for the next (graph-replayed) launch.
                g_sum_dev2 = 0.0f;
                g_sum_css2 = 0.0f;
                __threadfence();
                g_ticket = 0u;
            }
        }
    }
}

extern "C" void kernel_launch(void* const* d_in, const int* in_sizes, int n_in,
                              void* d_out, int out_size)
{
    const float* css   = (const float*)d_in[0];  // (4, DIM)
    const float* narr  = (const float*)d_in[1];  // (DIM,)
    const float* tonic = (const float*)d_in[2];  // (DIM,)
    const float* fast  = (const float*)d_in[3];  // scalar
    const float* slow  = (const float*)d_in[4];  // scalar
    float* out = (float*)d_out;

    ni_fused_kernel<<<BLOCKS, THREADS>>>(css, narr, tonic, fast, slow, out);
}

// round 8
// speedup vs baseline: 1.0197x; 1.0197x over previous
#include <cuda_runtime.h>
#include <math.h>

#define DIM 16777216
#define NVEC (DIM / 4)          // 4,194,304 float4 elements
#define THREADS 256
#define BLOCKS (NVEC / THREADS) // 16384

// Zero-initialized at module load; the last finishing block resets them at the
// end of every launch, so each launch sees zeros (graph-replay deterministic).
__device__ float        g_sum_dev2;
__device__ float        g_sum_css2;
__device__ unsigned int g_ticket;

__global__ void __launch_bounds__(THREADS) ni_fused_kernel(
    const float* __restrict__ css_in,   // (4, DIM)
    const float* __restrict__ narr,     // (DIM,)
    const float* __restrict__ tonic,    // (DIM,)
    const float* __restrict__ fast_p,   // scalar
    const float* __restrict__ slow_p,   // scalar
    float* __restrict__ out)            // [0:DIM)=new_narrative, [DIM:2DIM)=velocity, [2DIM:2DIM+3)=scalars
{
    const int i = blockIdx.x * blockDim.x + threadIdx.x;  // float4 index

    const float4* a0 = reinterpret_cast<const float4*>(css_in);
    const float4* a1 = a0 + NVEC;
    const float4* a2 = a1 + NVEC;
    const float4* a3 = a2 + NVEC;
    const float4* n4 = reinterpret_cast<const float4*>(narr);
    const float4* t4 = reinterpret_cast<const float4*>(tonic);
    float4* out_nn  = reinterpret_cast<float4*>(out);
    float4* out_vel = out_nn + NVEC;

    float4 v0 = a0[i];
    float4 v1 = a1[i];
    float4 v2 = a2[i];
    float4 v3 = a3[i];
    float4 n  = n4[i];
    float4 t  = t4[i];

    float dev2 = 0.0f;
    float c2   = 0.0f;
    float4 nn, vel;

    {
        float css = (v0.x + v1.x + v2.x + v3.x) * 0.25f;
        float d   = css - n.x;
        dev2 = fmaf(d, d, dev2);  c2 = fmaf(css, css, c2);
        nn.x  = fmaf(n.x, 0.99f, fmaf(css, 0.01f, t.x));
        vel.x = nn.x - n.x;
    }
    {
        float css = (v0.y + v1.y + v2.y + v3.y) * 0.25f;
        float d   = css - n.y;
        dev2 = fmaf(d, d, dev2);  c2 = fmaf(css, css, c2);
        nn.y  = fmaf(n.y, 0.99f, fmaf(css, 0.01f, t.y));
        vel.y = nn.y - n.y;
    }
    {
        float css = (v0.z + v1.z + v2.z + v3.z) * 0.25f;
        float d   = css - n.z;
        dev2 = fmaf(d, d, dev2);  c2 = fmaf(css, css, c2);
        nn.z  = fmaf(n.z, 0.99f, fmaf(css, 0.01f, t.z));
        vel.z = nn.z - n.z;
    }
    {
        float css = (v0.w + v1.w + v2.w + v3.w) * 0.25f;
        float d   = css - n.w;
        dev2 = fmaf(d, d, dev2);  c2 = fmaf(css, css, c2);
        nn.w  = fmaf(n.w, 0.99f, fmaf(css, 0.01f, t.w));
        vel.w = nn.w - n.w;
    }

    out_nn[i]  = nn;
    out_vel[i] = vel;

    // Warp-level reduce both sums
    #pragma unroll
    for (int off = 16; off > 0; off >>= 1) {
        dev2 += __shfl_down_sync(0xFFFFFFFFu, dev2, off);
        c2   += __shfl_down_sync(0xFFFFFFFFu, c2,   off);
    }

    __shared__ float s_dev[THREADS / 32];
    __shared__ float s_css[THREADS / 32];
    const int lane = threadIdx.x & 31;
    const int wid  = threadIdx.x >> 5;
    if (lane == 0) { s_dev[wid] = dev2; s_css[wid] = c2; }
    __syncthreads();

    if (wid == 0) {
        dev2 = (lane < THREADS / 32) ? s_dev[lane] : 0.0f;
        c2   = (lane < THREADS / 32) ? s_css[lane] : 0.0f;
        #pragma unroll
        for (int off = 4; off > 0; off >>= 1) {
            dev2 += __shfl_down_sync(0xFFFFFFFFu, dev2, off);
            c2   += __shfl_down_sync(0xFFFFFFFFu, c2,   off);
        }
        if (lane == 0) {
            atomicAdd(&g_sum_dev2, dev2);
            atomicAdd(&g_sum_css2, c2);
            __threadfence();  // make sums visible before ticket increment
            unsigned int tk = atomicAdd(&g_ticket, 1u);
            if (tk == (unsigned int)(BLOCKS - 1)) {
                // Last block: compute scalar epilogue, then reset state.
                const float sum_dev2 = atomicAdd(&g_sum_dev2, 0.0f);
                const float sum_css2 = atomicAdd(&g_sum_css2, 0.0f);
                const float dev_norm = sqrtf(sum_dev2);
                const float css_norm = sqrtf(sum_css2);
                const float fast = fast_p[0];
                const float slow = slow_p[0];

                const float consistency_loss = 0.1f * dev_norm;

                const float input_gate = fminf(1.0f, css_norm);
                const float delta_fast = 0.01f / (1.0f + fast * 5.0f) * input_gate;
                const float fast_new   = fminf(fast * 0.9995f + delta_fast, 0.7f);

                const float schema_fit  = fminf(fmaxf(1.0f - dev_norm, 0.0f), 1.0f);
                const float schema_mult = 1.0f + 15.0f * schema_fit * schema_fit;
                const float delta_slow  = 0.001f / (1.0f + slow * 5.0f) * schema_mult;
                const float slow_new    = fminf(slow + delta_slow, 1.0f);

                const float identity_strength = fminf(fast_new + slow_new, 1.0f);

                out[2 * DIM + 0] = consistency_loss;
                out[2 * DIM + 1] = identity_strength;
                out[2 * DIM + 2] = dev_norm;

                // Reset for the next (graph-replayed) launch.
                g_sum_dev2 = 0.0f;
                g_sum_css2 = 0.0f;
                __threadfence();
                g_ticket = 0u;
            }
        }
    }
}

extern "C" void kernel_launch(void* const* d_in, const int* in_sizes, int n_in,
                              void* d_out, int out_size)
{
    const float* css   = (const float*)d_in[0];  // (4, DIM)
    const float* narr  = (const float*)d_in[1];  // (DIM,)
    const float* tonic = (const float*)d_in[2];  // (DIM,)
    const float* fast  = (const float*)d_in[3];  // scalar
    const float* slow  = (const float*)d_in[4];  // scalar
    float* out = (float*)d_out;

    ni_fused_kernel<<<BLOCKS, THREADS>>>(css, narr, tonic, fast, slow, out);
}

// round 9
// speedup vs baseline: 1.0283x; 1.0084x over previous
#include <cuda_runtime.h>
#include <math.h>

#define DIM 16777216
#define NVEC (DIM / 4)          // 4,194,304 float4 elements
#define THREADS 256
#define BLOCKS (NVEC / THREADS) // 16384

// Zero-initialized at module load; the last finishing block resets them at the
// end of every launch, so each launch sees zeros (graph-replay deterministic).
__device__ float        g_sum_dev2;
__device__ float        g_sum_css2;
__device__ unsigned int g_ticket;

// acq_rel fetch-add at GPU scope: orders this thread's prior (relaxed) atomic
// adds before the increment, and synchronizes-with all other blocks' releases
// when the returned value shows we are last. No MEMBAR / CCTL.IVALL emitted.
__device__ __forceinline__ unsigned int ticket_acq_rel_inc(unsigned int* p) {
    unsigned int old;
    asm volatile("atom.add.acq_rel.gpu.global.u32 %0, [%1], 1;"
                 : "=r"(old) : "l"(p) : "memory");
    return old;
}

__global__ void __launch_bounds__(THREADS) ni_fused_kernel(
    const float* __restrict__ css_in,   // (4, DIM)
    const float* __restrict__ narr,     // (DIM,)
    const float* __restrict__ tonic,    // (DIM,)
    const float* __restrict__ fast_p,   // scalar
    const float* __restrict__ slow_p,   // scalar
    float* __restrict__ out)            // [0:DIM)=new_narrative, [DIM:2DIM)=velocity, [2DIM:2DIM+3)=scalars
{
    const int i = blockIdx.x * blockDim.x + threadIdx.x;  // float4 index

    const float4* a0 = reinterpret_cast<const float4*>(css_in);
    const float4* a1 = a0 + NVEC;
    const float4* a2 = a1 + NVEC;
    const float4* a3 = a2 + NVEC;
    const float4* n4 = reinterpret_cast<const float4*>(narr);
    const float4* t4 = reinterpret_cast<const float4*>(tonic);
    float4* out_nn  = reinterpret_cast<float4*>(out);
    float4* out_vel = out_nn + NVEC;

    float4 v0 = a0[i];
    float4 v1 = a1[i];
    float4 v2 = a2[i];
    float4 v3 = a3[i];
    float4 n  = n4[i];
    float4 t  = t4[i];

    float dev2 = 0.0f;
    float c2   = 0.0f;
    float4 nn, vel;

    {
        float css = (v0.x + v1.x + v2.x + v3.x) * 0.25f;
        float d   = css - n.x;
        dev2 = fmaf(d, d, dev2);  c2 = fmaf(css, css, c2);
        nn.x  = fmaf(n.x, 0.99f, fmaf(css, 0.01f, t.x));
        vel.x = nn.x - n.x;
    }
    {
        float css = (v0.y + v1.y + v2.y + v3.y) * 0.25f;
        float d   = css - n.y;
        dev2 = fmaf(d, d, dev2);  c2 = fmaf(css, css, c2);
        nn.y  = fmaf(n.y, 0.99f, fmaf(css, 0.01f, t.y));
        vel.y = nn.y - n.y;
    }
    {
        float css = (v0.z + v1.z + v2.z + v3.z) * 0.25f;
        float d   = css - n.z;
        dev2 = fmaf(d, d, dev2);  c2 = fmaf(css, css, c2);
        nn.z  = fmaf(n.z, 0.99f, fmaf(css, 0.01f, t.z));
        vel.z = nn.z - n.z;
    }
    {
        float css = (v0.w + v1.w + v2.w + v3.w) * 0.25f;
        float d   = css - n.w;
        dev2 = fmaf(d, d, dev2);  c2 = fmaf(css, css, c2);
        nn.w  = fmaf(n.w, 0.99f, fmaf(css, 0.01f, t.w));
        vel.w = nn.w - n.w;
    }

    out_nn[i]  = nn;
    out_vel[i] = vel;

    // Warp-level reduce both sums
    #pragma unroll
    for (int off = 16; off > 0; off >>= 1) {
        dev2 += __shfl_down_sync(0xFFFFFFFFu, dev2, off);
        c2   += __shfl_down_sync(0xFFFFFFFFu, c2,   off);
    }

    __shared__ float s_dev[THREADS / 32];
    __shared__ float s_css[THREADS / 32];
    const int lane = threadIdx.x & 31;
    const int wid  = threadIdx.x >> 5;
    if (lane == 0) { s_dev[wid] = dev2; s_css[wid] = c2; }
    __syncthreads();

    if (wid == 0) {
        dev2 = (lane < THREADS / 32) ? s_dev[lane] : 0.0f;
        c2   = (lane < THREADS / 32) ? s_css[lane] : 0.0f;
        #pragma unroll
        for (int off = 4; off > 0; off >>= 1) {
            dev2 += __shfl_down_sync(0xFFFFFFFFu, dev2, off);
            c2   += __shfl_down_sync(0xFFFFFFFFu, c2,   off);
        }
        if (lane == 0) {
            atomicAdd(&g_sum_dev2, dev2);          // relaxed, L2-resident
            atomicAdd(&g_sum_css2, c2);            // relaxed, L2-resident
            unsigned int tk = ticket_acq_rel_inc(&g_ticket);  // acq_rel, no membar
            if (tk == (unsigned int)(BLOCKS - 1)) {
                // Last block: all other blocks' sum-adds happen-before here.
                const float sum_dev2 = atomicAdd(&g_sum_dev2, 0.0f);
                const float sum_css2 = atomicAdd(&g_sum_css2, 0.0f);
                const float dev_norm = sqrtf(sum_dev2);
                const float css_norm = sqrtf(sum_css2);
                const float fast = fast_p[0];
                const float slow = slow_p[0];

                const float consistency_loss = 0.1f * dev_norm;

                const float input_gate = fminf(1.0f, css_norm);
                const float delta_fast = 0.01f / (1.0f + fast * 5.0f) * input_gate;
                const float fast_new   = fminf(fast * 0.9995f + delta_fast, 0.7f);

                const float schema_fit  = fminf(fmaxf(1.0f - dev_norm, 0.0f), 1.0f);
                const float schema_mult = 1.0f + 15.0f * schema_fit * schema_fit;
                const float delta_slow  = 0.001f / (1.0f + slow * 5.0f) * schema_mult;
                const float slow_new    = fminf(slow + delta_slow, 1.0f);

                const float identity_strength = fminf(fast_new + slow_new, 1.0f);

                out[2 * DIM + 0] = consistency_loss;
                out[2 * DIM + 1] = identity_strength;
                out[2 * DIM + 2] = dev_norm;

                // Reset for the next (graph-replayed) launch. Ordering with the
                // next launch's reads is guaranteed by the kernel boundary.
                g_sum_dev2 = 0.0f;
                g_sum_css2 = 0.0f;
                g_ticket   = 0u;
            }
        }
    }
}

extern "C" void kernel_launch(void* const* d_in, const int* in_sizes, int n_in,
                              void* d_out, int out_size)
{
    const float* css   = (const float*)d_in[0];  // (4, DIM)
    const float* narr  = (const float*)d_in[1];  // (DIM,)
    const float* tonic = (const float*)d_in[2];  // (DIM,)
    const float* fast  = (const float*)d_in[3];  // scalar
    const float* slow  = (const float*)d_in[4];  // scalar
    float* out = (float*)d_out;

    ni_fused_kernel<<<BLOCKS, THREADS>>>(css, narr, tonic, fast, slow, out);
}

// round 10
// speedup vs baseline: 1.0717x; 1.0422x over previous
#include <cuda_runtime.h>
#include <math.h>

#define DIM 16777216
#define NVEC (DIM / 4)          // 4,194,304 float4 elements
#define THREADS 256
#define BLOCKS (NVEC / THREADS) // 16384

// Zero-initialized at module load. The epilogue kernel resets them to zero
// after consuming them, so every launch (and every graph replay) starts from
// zeros — deterministic without any zeroing kernel.
__device__ float g_sum_dev2;
__device__ float g_sum_css2;

__global__ void __launch_bounds__(THREADS) ni_main_kernel(
    const float* __restrict__ css_in,   // (4, DIM)
    const float* __restrict__ narr,     // (DIM,)
    const float* __restrict__ tonic,    // (DIM,)
    float* __restrict__ out)            // [0:DIM)=new_narrative, [DIM:2DIM)=velocity
{
    const int i = blockIdx.x * blockDim.x + threadIdx.x;  // float4 index

    const float4* a0 = reinterpret_cast<const float4*>(css_in);
    const float4* a1 = a0 + NVEC;
    const float4* a2 = a1 + NVEC;
    const float4* a3 = a2 + NVEC;
    const float4* n4 = reinterpret_cast<const float4*>(narr);
    const float4* t4 = reinterpret_cast<const float4*>(tonic);
    float4* out_nn  = reinterpret_cast<float4*>(out);
    float4* out_vel = out_nn + NVEC;

    float4 v0 = a0[i];
    float4 v1 = a1[i];
    float4 v2 = a2[i];
    float4 v3 = a3[i];
    float4 n  = n4[i];
    float4 t  = t4[i];

    float dev2 = 0.0f;
    float c2   = 0.0f;
    float4 nn, vel;

    {
        float css = (v0.x + v1.x + v2.x + v3.x) * 0.25f;
        float d   = css - n.x;
        dev2 = fmaf(d, d, dev2);  c2 = fmaf(css, css, c2);
        nn.x  = fmaf(n.x, 0.99f, fmaf(css, 0.01f, t.x));
        vel.x = nn.x - n.x;
    }
    {
        float css = (v0.y + v1.y + v2.y + v3.y) * 0.25f;
        float d   = css - n.y;
        dev2 = fmaf(d, d, dev2);  c2 = fmaf(css, css, c2);
        nn.y  = fmaf(n.y, 0.99f, fmaf(css, 0.01f, t.y));
        vel.y = nn.y - n.y;
    }
    {
        float css = (v0.z + v1.z + v2.z + v3.z) * 0.25f;
        float d   = css - n.z;
        dev2 = fmaf(d, d, dev2);  c2 = fmaf(css, css, c2);
        nn.z  = fmaf(n.z, 0.99f, fmaf(css, 0.01f, t.z));
        vel.z = nn.z - n.z;
    }
    {
        float css = (v0.w + v1.w + v2.w + v3.w) * 0.25f;
        float d   = css - n.w;
        dev2 = fmaf(d, d, dev2);  c2 = fmaf(css, css, c2);
        nn.w  = fmaf(n.w, 0.99f, fmaf(css, 0.01f, t.w));
        vel.w = nn.w - n.w;
    }

    out_nn[i]  = nn;
    out_vel[i] = vel;

    // Warp-level reduce both sums
    #pragma unroll
    for (int off = 16; off > 0; off >>= 1) {
        dev2 += __shfl_down_sync(0xFFFFFFFFu, dev2, off);
        c2   += __shfl_down_sync(0xFFFFFFFFu, c2,   off);
    }

    __shared__ float s_dev[THREADS / 32];
    __shared__ float s_css[THREADS / 32];
    const int lane = threadIdx.x & 31;
    const int wid  = threadIdx.x >> 5;
    if (lane == 0) { s_dev[wid] = dev2; s_css[wid] = c2; }
    __syncthreads();

    if (wid == 0) {
        dev2 = (lane < THREADS / 32) ? s_dev[lane] : 0.0f;
        c2   = (lane < THREADS / 32) ? s_css[lane] : 0.0f;
        #pragma unroll
        for (int off = 4; off > 0; off >>= 1) {
            dev2 += __shfl_down_sync(0xFFFFFFFFu, dev2, off);
            c2   += __shfl_down_sync(0xFFFFFFFFu, c2,   off);
        }
        if (lane == 0) {
            atomicAdd(&g_sum_dev2, dev2);   // relaxed RED, fire-and-forget
            atomicAdd(&g_sum_css2, c2);
        }
    }
}

__global__ void ni_epilogue_kernel(const float* __restrict__ fast_p,
                                   const float* __restrict__ slow_p,
                                   float* __restrict__ out)
{
    const float sum_dev2 = g_sum_dev2;
    const float sum_css2 = g_sum_css2;
    const float dev_norm = sqrtf(sum_dev2);
    const float css_norm = sqrtf(sum_css2);
    const float fast = fast_p[0];
    const float slow = slow_p[0];

    const float consistency_loss = 0.1f * dev_norm;

    const float input_gate = fminf(1.0f, css_norm);
    const float delta_fast = 0.01f / (1.0f + fast * 5.0f) * input_gate;
    const float fast_new   = fminf(fast * 0.9995f + delta_fast, 0.7f);

    const float schema_fit  = fminf(fmaxf(1.0f - dev_norm, 0.0f), 1.0f);
    const float schema_mult = 1.0f + 15.0f * schema_fit * schema_fit;
    const float delta_slow  = 0.001f / (1.0f + slow * 5.0f) * schema_mult;
    const float slow_new    = fminf(slow + delta_slow, 1.0f);

    const float identity_strength = fminf(fast_new + slow_new, 1.0f);

    out[2 * DIM + 0] = consistency_loss;
    out[2 * DIM + 1] = identity_strength;
    out[2 * DIM + 2] = dev_norm;

    // Reset accumulators for the next launch / graph replay.
    g_sum_dev2 = 0.0f;
    g_sum_css2 = 0.0f;
}

extern "C" void kernel_launch(void* const* d_in, const int* in_sizes, int n_in,
                              void* d_out, int out_size)
{
    const float* css   = (const float*)d_in[0];  // (4, DIM)
    const float* narr  = (const float*)d_in[1];  // (DIM,)
    const float* tonic = (const float*)d_in[2];  // (DIM,)
    const float* fast  = (const float*)d_in[3];  // scalar
    const float* slow  = (const float*)d_in[4];  // scalar
    float* out = (float*)d_out;

    ni_main_kernel<<<BLOCKS, THREADS>>>(css, narr, tonic, out);
    ni_epilogue_kernel<<<1, 1>>>(fast, slow, out);
}

// round 12
// speedup vs baseline: 1.0721x; 1.0004x over previous
#include <cuda_runtime.h>
#include <math.h>

#define DIM 16777216
#define NVEC (DIM / 4)          // 4,194,304 float4 elements
#define THREADS 256
#define BLOCKS (NVEC / THREADS) // 16384

// Zero-initialized at module load. The epilogue kernel resets them to zero
// after consuming them, so every launch (and every graph replay) starts from
// zeros — deterministic without any zeroing kernel.
__device__ float g_sum_dev2;
__device__ float g_sum_css2;

__global__ void __launch_bounds__(THREADS) ni_main_kernel(
    const float* __restrict__ css_in,   // (4, DIM)
    const float* __restrict__ narr,     // (DIM,)
    const float* __restrict__ tonic,    // (DIM,)
    float* __restrict__ out)            // [0:DIM)=new_narrative, [DIM:2DIM)=velocity
{
    const int i = blockIdx.x * blockDim.x + threadIdx.x;  // float4 index

    const float4* a0 = reinterpret_cast<const float4*>(css_in);
    const float4* a1 = a0 + NVEC;
    const float4* a2 = a1 + NVEC;
    const float4* a3 = a2 + NVEC;
    const float4* n4 = reinterpret_cast<const float4*>(narr);
    const float4* t4 = reinterpret_cast<const float4*>(tonic);
    float4* out_nn  = reinterpret_cast<float4*>(out);
    float4* out_vel = out_nn + NVEC;

    float4 v0 = a0[i];
    float4 v1 = a1[i];
    float4 v2 = a2[i];
    float4 v3 = a3[i];
    float4 n  = n4[i];
    float4 t  = t4[i];

    float dev2 = 0.0f;
    float c2   = 0.0f;
    float4 nn, vel;

    {
        float css = (v0.x + v1.x + v2.x + v3.x) * 0.25f;
        float d   = css - n.x;
        dev2 = fmaf(d, d, dev2);  c2 = fmaf(css, css, c2);
        nn.x  = fmaf(n.x, 0.99f, fmaf(css, 0.01f, t.x));
        vel.x = nn.x - n.x;
    }
    {
        float css = (v0.y + v1.y + v2.y + v3.y) * 0.25f;
        float d   = css - n.y;
        dev2 = fmaf(d, d, dev2);  c2 = fmaf(css, css, c2);
        nn.y  = fmaf(n.y, 0.99f, fmaf(css, 0.01f, t.y));
        vel.y = nn.y - n.y;
    }
    {
        float css = (v0.z + v1.z + v2.z + v3.z) * 0.25f;
        float d   = css - n.z;
        dev2 = fmaf(d, d, dev2);  c2 = fmaf(css, css, c2);
        nn.z  = fmaf(n.z, 0.99f, fmaf(css, 0.01f, t.z));
        vel.z = nn.z - n.z;
    }
    {
        float css = (v0.w + v1.w + v2.w + v3.w) * 0.25f;
        float d   = css - n.w;
        dev2 = fmaf(d, d, dev2);  c2 = fmaf(css, css, c2);
        nn.w  = fmaf(n.w, 0.99f, fmaf(css, 0.01f, t.w));
        vel.w = nn.w - n.w;
    }

    out_nn[i]  = nn;
    out_vel[i] = vel;

    // Warp-level reduce both sums
    #pragma unroll
    for (int off = 16; off > 0; off >>= 1) {
        dev2 += __shfl_down_sync(0xFFFFFFFFu, dev2, off);
        c2   += __shfl_down_sync(0xFFFFFFFFu, c2,   off);
    }

    __shared__ float s_dev[THREADS / 32];
    __shared__ float s_css[THREADS / 32];
    const int lane = threadIdx.x & 31;
    const int wid  = threadIdx.x >> 5;
    if (lane == 0) { s_dev[wid] = dev2; s_css[wid] = c2; }
    __syncthreads();

    if (wid == 0) {
        dev2 = (lane < THREADS / 32) ? s_dev[lane] : 0.0f;
        c2   = (lane < THREADS / 32) ? s_css[lane] : 0.0f;
        #pragma unroll
        for (int off = 4; off > 0; off >>= 1) {
            dev2 += __shfl_down_sync(0xFFFFFFFFu, dev2, off);
            c2   += __shfl_down_sync(0xFFFFFFFFu, c2,   off);
        }
        if (lane == 0) {
            atomicAdd(&g_sum_dev2, dev2);   // relaxed RED, fire-and-forget
            atomicAdd(&g_sum_css2, c2);
        }
    }
}

__global__ void ni_epilogue_kernel(const float* __restrict__ fast_p,
                                   const float* __restrict__ slow_p,
                                   float* __restrict__ out)
{
    // PDL: we may have been launched while the primary grid is still running.
    // Block until the primary grid completes (implicit trigger at its exit),
    // which also makes its atomic updates to g_sum_* visible.
    cudaGridDependencySynchronize();

    const float sum_dev2 = g_sum_dev2;
    const float sum_css2 = g_sum_css2;
    const float dev_norm = sqrtf(sum_dev2);
    const float css_norm = sqrtf(sum_css2);
    const float fast = fast_p[0];
    const float slow = slow_p[0];

    const float consistency_loss = 0.1f * dev_norm;

    const float input_gate = fminf(1.0f, css_norm);
    const float delta_fast = 0.01f / (1.0f + fast * 5.0f) * input_gate;
    const float fast_new   = fminf(fast * 0.9995f + delta_fast, 0.7f);

    const float schema_fit  = fminf(fmaxf(1.0f - dev_norm, 0.0f), 1.0f);
    const float schema_mult = 1.0f + 15.0f * schema_fit * schema_fit;
    const float delta_slow  = 0.001f / (1.0f + slow * 5.0f) * schema_mult;
    const float slow_new    = fminf(slow + delta_slow, 1.0f);

    const float identity_strength = fminf(fast_new + slow_new, 1.0f);

    out[2 * DIM + 0] = consistency_loss;
    out[2 * DIM + 1] = identity_strength;
    out[2 * DIM + 2] = dev_norm;

    // Reset accumulators for the next launch / graph replay.
    g_sum_dev2 = 0.0f;
    g_sum_css2 = 0.0f;
}

extern "C" void kernel_launch(void* const* d_in, const int* in_sizes, int n_in,
                              void* d_out, int out_size)
{
    const float* css   = (const float*)d_in[0];  // (4, DIM)
    const float* narr  = (const float*)d_in[1];  // (DIM,)
    const float* tonic = (const float*)d_in[2];  // (DIM,)
    const float* fast  = (const float*)d_in[3];  // scalar
    const float* slow  = (const float*)d_in[4];  // scalar
    float* out = (float*)d_out;

    ni_main_kernel<<<BLOCKS, THREADS>>>(css, narr, tonic, out);

    // Epilogue with Programmatic Dependent Launch: its launch latency overlaps
    // the primary's tail; cudaGridDependencySynchronize() inside enforces the
    // data dependency.
    cudaLaunchConfig_t cfg = {};
    cfg.gridDim  = dim3(1, 1, 1);
    cfg.blockDim = dim3(1, 1, 1);
    cfg.dynamicSmemBytes = 0;
    cfg.stream = 0;  // same (default) stream as the primary launch

    cudaLaunchAttribute attrs[1];
    attrs[0].id = cudaLaunchAttributeProgrammaticStreamSerialization;
    attrs[0].val.programmaticStreamSerializationAllowed = 1;
    cfg.attrs = attrs;
    cfg.numAttrs = 1;

    cudaLaunchKernelEx(&cfg, ni_epilogue_kernel, fast, slow, out);
}

// round 13
// speedup vs baseline: 1.0777x; 1.0052x over previous
#include <cuda_runtime.h>
#include <math.h>

#define DIM 16777216
#define NVEC (DIM / 4)          // 4,194,304 float4 elements
#define THREADS 256
#define BLOCKS (NVEC / THREADS) // 16384

// Zero-initialized at module load. The epilogue kernel resets them to zero
// after consuming them, so every launch (and every graph replay) starts from
// zeros — deterministic without any zeroing kernel.
__device__ float g_sum_dev2;
__device__ float g_sum_css2;

__global__ void __launch_bounds__(THREADS) ni_main_kernel(
    const float* __restrict__ css_in,   // (4, DIM)
    const float* __restrict__ narr,     // (DIM,)
    const float* __restrict__ tonic,    // (DIM,)
    float* __restrict__ out)            // [0:DIM)=new_narrative, [DIM:2DIM)=velocity
{
    // PDL: fire the programmatic trigger immediately. Once every block has
    // triggered, the dependent epilogue kernel may LAUNCH (its prologue and
    // scalar loads overlap our streaming work); it still waits for our full
    // grid completion inside cudaGridDependencySynchronize() before reading
    // the accumulators.
    cudaTriggerProgrammaticLaunchCompletion();

    const int i = blockIdx.x * blockDim.x + threadIdx.x;  // float4 index

    const float4* a0 = reinterpret_cast<const float4*>(css_in);
    const float4* a1 = a0 + NVEC;
    const float4* a2 = a1 + NVEC;
    const float4* a3 = a2 + NVEC;
    const float4* n4 = reinterpret_cast<const float4*>(narr);
    const float4* t4 = reinterpret_cast<const float4*>(tonic);
    float4* out_nn  = reinterpret_cast<float4*>(out);
    float4* out_vel = out_nn + NVEC;

    float4 v0 = a0[i];
    float4 v1 = a1[i];
    float4 v2 = a2[i];
    float4 v3 = a3[i];
    float4 n  = n4[i];
    float4 t  = t4[i];

    float dev2 = 0.0f;
    float c2   = 0.0f;
    float4 nn, vel;

    {
        float css = (v0.x + v1.x + v2.x + v3.x) * 0.25f;
        float d   = css - n.x;
        dev2 = fmaf(d, d, dev2);  c2 = fmaf(css, css, c2);
        nn.x  = fmaf(n.x, 0.99f, fmaf(css, 0.01f, t.x));
        vel.x = nn.x - n.x;
    }
    {
        float css = (v0.y + v1.y + v2.y + v3.y) * 0.25f;
        float d   = css - n.y;
        dev2 = fmaf(d, d, dev2);  c2 = fmaf(css, css, c2);
        nn.y  = fmaf(n.y, 0.99f, fmaf(css, 0.01f, t.y));
        vel.y = nn.y - n.y;
    }
    {
        float css = (v0.z + v1.z + v2.z + v3.z) * 0.25f;
        float d   = css - n.z;
        dev2 = fmaf(d, d, dev2);  c2 = fmaf(css, css, c2);
        nn.z  = fmaf(n.z, 0.99f, fmaf(css, 0.01f, t.z));
        vel.z = nn.z - n.z;
    }
    {
        float css = (v0.w + v1.w + v2.w + v3.w) * 0.25f;
        float d   = css - n.w;
        dev2 = fmaf(d, d, dev2);  c2 = fmaf(css, css, c2);
        nn.w  = fmaf(n.w, 0.99f, fmaf(css, 0.01f, t.w));
        vel.w = nn.w - n.w;
    }

    out_nn[i]  = nn;
    out_vel[i] = vel;

    // Warp-level reduce both sums
    #pragma unroll
    for (int off = 16; off > 0; off >>= 1) {
        dev2 += __shfl_down_sync(0xFFFFFFFFu, dev2, off);
        c2   += __shfl_down_sync(0xFFFFFFFFu, c2,   off);
    }

    __shared__ float s_dev[THREADS / 32];
    __shared__ float s_css[THREADS / 32];
    const int lane = threadIdx.x & 31;
    const int wid  = threadIdx.x >> 5;
    if (lane == 0) { s_dev[wid] = dev2; s_css[wid] = c2; }
    __syncthreads();

    if (wid == 0) {
        dev2 = (lane < THREADS / 32) ? s_dev[lane] : 0.0f;
        c2   = (lane < THREADS / 32) ? s_css[lane] : 0.0f;
        #pragma unroll
        for (int off = 4; off > 0; off >>= 1) {
            dev2 += __shfl_down_sync(0xFFFFFFFFu, dev2, off);
            c2   += __shfl_down_sync(0xFFFFFFFFu, c2,   off);
        }
        if (lane == 0) {
            atomicAdd(&g_sum_dev2, dev2);   // relaxed RED, fire-and-forget
            atomicAdd(&g_sum_css2, c2);
        }
    }
}

__global__ void ni_epilogue_kernel(const float* __restrict__ fast_p,
                                   const float* __restrict__ slow_p,
                                   float* __restrict__ out)
{
    // Independent of the primary grid's writes — load while it still runs.
    const float fast = fast_p[0];
    const float slow = slow_p[0];

    // Block until the primary grid completes; all its memory operations
    // (including the RED atomics into g_sum_*) are then visible.
    cudaGridDependencySynchronize();

    const float sum_dev2 = g_sum_dev2;
    const float sum_css2 = g_sum_css2;
    const float dev_norm = sqrtf(sum_dev2);
    const float css_norm = sqrtf(sum_css2);

    const float consistency_loss = 0.1f * dev_norm;

    const float input_gate = fminf(1.0f, css_norm);
    const float delta_fast = 0.01f / (1.0f + fast * 5.0f) * input_gate;
    const float fast_new   = fminf(fast * 0.9995f + delta_fast, 0.7f);

    const float schema_fit  = fminf(fmaxf(1.0f - dev_norm, 0.0f), 1.0f);
    const float schema_mult = 1.0f + 15.0f * schema_fit * schema_fit;
    const float delta_slow  = 0.001f / (1.0f + slow * 5.0f) * schema_mult;
    const float slow_new    = fminf(slow + delta_slow, 1.0f);

    const float identity_strength = fminf(fast_new + slow_new, 1.0f);

    out[2 * DIM + 0] = consistency_loss;
    out[2 * DIM + 1] = identity_strength;
    out[2 * DIM + 2] = dev_norm;

    // Reset accumulators for the next launch / graph replay.
    g_sum_dev2 = 0.0f;
    g_sum_css2 = 0.0f;
}

extern "C" void kernel_launch(void* const* d_in, const int* in_sizes, int n_in,
                              void* d_out, int out_size)
{
    const float* css   = (const float*)d_in[0];  // (4, DIM)
    const float* narr  = (const float*)d_in[1];  // (DIM,)
    const float* tonic = (const float*)d_in[2];  // (DIM,)
    const float* fast  = (const float*)d_in[3];  // scalar
    const float* slow  = (const float*)d_in[4];  // scalar
    float* out = (float*)d_out;

    ni_main_kernel<<<BLOCKS, THREADS>>>(css, narr, tonic, out);

    // Epilogue with Programmatic Dependent Launch: because every primary block
    // triggers at entry, this node launches while the primary is still
    // streaming; cudaGridDependencySynchronize() inside enforces the data
    // dependency at primary-grid completion.
    cudaLaunchConfig_t cfg = {};
    cfg.gridDim  = dim3(1, 1, 1);
    cfg.blockDim = dim3(1, 1, 1);
    cfg.dynamicSmemBytes = 0;
    cfg.stream = 0;  // same (default) stream as the primary launch

    cudaLaunchAttribute attrs[1];
    attrs[0].id = cudaLaunchAttributeProgrammaticStreamSerialization;
    attrs[0].val.programmaticStreamSerializationAllowed = 1;
    cfg.attrs = attrs;
    cfg.numAttrs = 1;

    cudaLaunchKernelEx(&cfg, ni_epilogue_kernel, fast, slow, out);
}